// round 2
// baseline (speedup 1.0000x reference)
#include <cuda_runtime.h>

// ---------------------------------------------------------------------------
// ContactMapGeneration: mean/s_obj stats + farthest point sampling + gather.
//
// FPS strategy: persistent kernel, 9 CTAs per batch x 16 batches = 144 CTAs
// (all co-resident on 148 SMs). Each thread keeps 22 points (x,y,z,D) in
// registers; per iteration: register-only distance update + min + argmax,
// block reduction, then a per-batch global spin barrier (monotone counter)
// to merge 9 partial argmaxes.
// ---------------------------------------------------------------------------

#define FPS_THREADS 512
#define BPB 9           // blocks per batch (16*9 = 144 <= 148 SMs)
#define PPT 22          // points per thread: 9*512*22 = 101376 >= 100000
#define MAXB 16
#define MAXNP 4096

#define NEG_SENT (-1e30f)
#define BIGF (1e10f)

// ---- device scratch (no allocations allowed) ----
__device__ int   g_cent[MAXB * MAXNP];
__device__ float g_pval[MAXB][2][BPB];
__device__ int   g_pidx[MAXB][2][BPB];
__device__ int   g_cnt[MAXB];
__device__ float g_meanv[MAXB][3];
__device__ float g_invs[MAXB];

__device__ __forceinline__ int ld_acquire(const int* p) {
    int v;
    asm volatile("ld.global.acquire.gpu.b32 %0, [%1];" : "=r"(v) : "l"(p) : "memory");
    return v;
}

// ---------------------------------------------------------------------------
// Kernel 1: per-batch mean of mesh; also resets the FPS barrier counters.
// ---------------------------------------------------------------------------
__global__ void stats_mean_kernel(const float* __restrict__ mesh, int N) {
    int b = blockIdx.x;
    if (threadIdx.x == 0) g_cnt[b] = 0;

    const float* p = mesh + (size_t)b * N * 3;
    float sx = 0.f, sy = 0.f, sz = 0.f;
    for (int i = threadIdx.x; i < N; i += blockDim.x) {
        sx += p[3 * i + 0];
        sy += p[3 * i + 1];
        sz += p[3 * i + 2];
    }
    #pragma unroll
    for (int o = 16; o; o >>= 1) {
        sx += __shfl_down_sync(0xffffffffu, sx, o);
        sy += __shfl_down_sync(0xffffffffu, sy, o);
        sz += __shfl_down_sync(0xffffffffu, sz, o);
    }
    __shared__ float sh[3][8];
    int w = threadIdx.x >> 5;
    if ((threadIdx.x & 31) == 0) { sh[0][w] = sx; sh[1][w] = sy; sh[2][w] = sz; }
    __syncthreads();
    if (threadIdx.x == 0) {
        float tx = 0.f, ty = 0.f, tz = 0.f;
        int nw = blockDim.x >> 5;
        for (int i = 0; i < nw; ++i) { tx += sh[0][i]; ty += sh[1][i]; tz += sh[2][i]; }
        float fn = (float)N;
        g_meanv[b][0] = tx / fn;
        g_meanv[b][1] = ty / fn;
        g_meanv[b][2] = tz / fn;
    }
}

// ---------------------------------------------------------------------------
// Kernel 2: s_obj = max ||p - mean||; store 1/s_obj.
// ---------------------------------------------------------------------------
__global__ void stats_sobj_kernel(const float* __restrict__ mesh, int N) {
    int b = blockIdx.x;
    const float* p = mesh + (size_t)b * N * 3;
    float cx = g_meanv[b][0], cy = g_meanv[b][1], cz = g_meanv[b][2];
    float mx = 0.f;
    for (int i = threadIdx.x; i < N; i += blockDim.x) {
        float dx = p[3 * i + 0] - cx;
        float dy = p[3 * i + 1] - cy;
        float dz = p[3 * i + 2] - cz;
        float d = dx * dx + dy * dy + dz * dz;
        mx = fmaxf(mx, d);
    }
    #pragma unroll
    for (int o = 16; o; o >>= 1)
        mx = fmaxf(mx, __shfl_down_sync(0xffffffffu, mx, o));
    __shared__ float sh[8];
    int w = threadIdx.x >> 5;
    if ((threadIdx.x & 31) == 0) sh[w] = mx;
    __syncthreads();
    if (threadIdx.x == 0) {
        int nw = blockDim.x >> 5;
        float t = 0.f;
        for (int i = 0; i < nw; ++i) t = fmaxf(t, sh[i]);
        g_invs[b] = 1.0f / sqrtf(t);
    }
}

// ---------------------------------------------------------------------------
// Kernel 3: persistent FPS. grid = B * BPB blocks, FPS_THREADS threads.
// ---------------------------------------------------------------------------
__global__ void __launch_bounds__(FPS_THREADS, 1)
fps_kernel(const float* __restrict__ mesh, const int* __restrict__ init_f,
           int N, int npoint) {
    int blk = blockIdx.x;
    int b = blk / BPB;
    int r = blk % BPB;
    int CH = (N + BPB - 1) / BPB;
    int start = r * CH;
    int t = threadIdx.x;
    const float* mb = mesh + (size_t)b * N * 3;

    // Load this thread's points into registers; distances start at BIG.
    float X[PPT], Y[PPT], Z[PPT], D[PPT];
    #pragma unroll
    for (int j = 0; j < PPT; ++j) {
        int l = t + j * FPS_THREADS;
        int p = start + l;
        if (l < CH && p < N) {
            X[j] = mb[3 * p + 0];
            Y[j] = mb[3 * p + 1];
            Z[j] = mb[3 * p + 2];
            D[j] = BIGF;
        } else {
            X[j] = 0.f; Y[j] = 0.f; Z[j] = 0.f;
            D[j] = NEG_SENT;   // never wins argmax, min keeps it
        }
    }

    __shared__ float s_c[3];
    __shared__ float s_wv[FPS_THREADS / 32];
    __shared__ int   s_wi[FPS_THREADS / 32];

    int f = 0;
    if (t == 0) f = init_f[b];

    for (int it = 0; it < npoint; ++it) {
        if (t == 0) {
            if (r == 0) g_cent[b * npoint + it] = f;
            const float* cp = mb + 3 * (size_t)f;
            s_c[0] = cp[0]; s_c[1] = cp[1]; s_c[2] = cp[2];
        }
        __syncthreads();
        if (it == npoint - 1) break;   // last centroid recorded; argmax unused

        float cx = s_c[0], cy = s_c[1], cz = s_c[2];

        // Register-resident distance update + running argmax.
        // Non-fused mul/add in ((dx^2+dy^2)+dz^2) order to match the
        // reference's fp32 rounding; strict > keeps first index per thread.
        float bv = NEG_SENT;
        int bj = 0;
        #pragma unroll
        for (int j = 0; j < PPT; ++j) {
            float dx = __fadd_rn(X[j], -cx);
            float dy = __fadd_rn(Y[j], -cy);
            float dz = __fadd_rn(Z[j], -cz);
            float d = __fadd_rn(__fadd_rn(__fmul_rn(dx, dx), __fmul_rn(dy, dy)),
                                __fmul_rn(dz, dz));
            float nd = fminf(D[j], d);
            D[j] = nd;
            if (nd > bv) { bv = nd; bj = j; }
        }
        int bidx = start + t + bj * FPS_THREADS;

        // Warp reduce with first-index tie-break.
        #pragma unroll
        for (int o = 16; o; o >>= 1) {
            float ov = __shfl_down_sync(0xffffffffu, bv, o);
            int   oi = __shfl_down_sync(0xffffffffu, bidx, o);
            if (ov > bv || (ov == bv && oi < bidx)) { bv = ov; bidx = oi; }
        }
        int w = t >> 5;
        if ((t & 31) == 0) { s_wv[w] = bv; s_wi[w] = bidx; }
        __syncthreads();

        if (t == 0) {
            #pragma unroll
            for (int i = 1; i < FPS_THREADS / 32; ++i) {
                float v = s_wv[i];
                int  ii = s_wi[i];
                if (v > bv || (v == bv && ii < bidx)) { bv = v; bidx = ii; }
            }
            int buf = it & 1;
            g_pval[b][buf][r] = bv;
            g_pidx[b][buf][r] = bidx;
            __threadfence();
            atomicAdd(&g_cnt[b], 1);
            int target = BPB * (it + 1);
            while (ld_acquire(&g_cnt[b]) < target) { }
            // Merge 9 partials; ascending r == ascending index ranges, so
            // strict > preserves first-index tie-breaking.
            float Gv = NEG_SENT;
            int Gi = 0;
            #pragma unroll
            for (int rr = 0; rr < BPB; ++rr) {
                float v = __ldcg(&g_pval[b][buf][rr]);
                int  ii = __ldcg(&g_pidx[b][buf][rr]);
                if (v > Gv) { Gv = v; Gi = ii; }
            }
            f = Gi;
        }
        // next iteration's top __syncthreads orders everything
    }
}

// ---------------------------------------------------------------------------
// Kernel 4: gather sampled points + contact map, normalize, write [B,np,4].
// ---------------------------------------------------------------------------
__global__ void gather_kernel(const float* __restrict__ mesh,
                              const float* __restrict__ cm,
                              float* __restrict__ out,
                              int N, int npoint, int B) {
    int i = blockIdx.x * blockDim.x + threadIdx.x;
    if (i >= B * npoint) return;
    int b = i / npoint;
    int idx = g_cent[i];
    const float* p = mesh + 3 * ((size_t)b * N + idx);
    float inv = g_invs[b];
    float4 o;
    o.x = cm[(size_t)b * N + idx];
    o.y = p[0] * inv;
    o.z = p[1] * inv;
    o.w = p[2] * inv;
    reinterpret_cast<float4*>(out)[i] = o;
}

// ---------------------------------------------------------------------------
extern "C" void kernel_launch(void* const* d_in, const int* in_sizes, int n_in,
                              void* d_out, int out_size) {
    const float* mesh = (const float*)d_in[0];
    const float* cm   = (const float*)d_in[1];
    const int*   init = (const int*)d_in[2];

    int B = in_sizes[2];                 // 16
    int N = in_sizes[0] / (3 * B);       // 100000
    int npoint = out_size / (4 * B);     // 1024

    stats_mean_kernel<<<B, 256>>>(mesh, N);
    stats_sobj_kernel<<<B, 256>>>(mesh, N);
    fps_kernel<<<B * BPB, FPS_THREADS>>>(mesh, init, N, npoint);

    int tot = B * npoint;
    gather_kernel<<<(tot + 255) / 256, 256>>>(mesh, cm, (float*)d_out,
                                              N, npoint, B);
}